// round 11
// baseline (speedup 1.0000x reference)
#include <cuda_runtime.h>
#include <cuda_bf16.h>

// Output[b,s,:] == mean(knowledge, axis=0) for every (b,s):
// top_k with max_chunks == K selects a permutation of ALL knowledge rows,
// so mean(take(knowledge, top_k), axis=1) == mean(knowledge, axis=0).
//
// R10 lesson: smem BYTES are the reduce cost, not barriers (private-sum
// variant regressed). This round = R9's best-measured shape (256 CTAs x
// 512 threads, 2 loads/thread) + shfl_xor(16) pre-combine (halves smem
// partials and traffic, 4 tree steps instead of 5) + branch-free stores.

#define E_DIM 512
#define K_ROWS 64
#define THREADS 512
#define COLS4 (E_DIM / 4)       // 128 float4 per full row
#define NCB 8                   // column blocks
#define CB4 (COLS4 / NCB)       // 16 float4 columns per block
#define ROWS_PER_CTA 128        // 32 row-blocks cover 4096 rows
#define NPART 16                // partials after shfl pre-combine

__global__ void __launch_bounds__(THREADS)
fused_mean_broadcast(const float4* __restrict__ knowledge4,
                     float4* __restrict__ out) {
    __shared__ float4 part[NPART * CB4];   // 16 partials x 16 cols, 4KB

    int t = threadIdx.x;
    int c = t & (CB4 - 1);      // column within block: 0..15
    int g = t >> 4;             // group 0..31: sums rows [2g, 2g+2)
    int w = t >> 5;             // warp 0..15

    int cb = blockIdx.x & (NCB - 1);   // column block 0..7
    int rb = blockIdx.x >> 3;          // row block 0..31
    int col = cb * CB4 + c;            // global float4 column

    // 2 independent front-batched loads per thread (coalesced).
    float4 a0 = knowledge4[(g * 2 + 0) * COLS4 + col];
    float4 a1 = knowledge4[(g * 2 + 1) * COLS4 + col];
    float4 s;
    s.x = a0.x + a1.x; s.y = a0.y + a1.y;
    s.z = a0.z + a1.z; s.w = a0.w + a1.w;

    // Lanes l and l+16 of a warp hold the same column for adjacent row
    // groups: one shfl_xor(16) merges them (32 partials -> 16, no smem).
    s.x += __shfl_xor_sync(0xffffffffu, s.x, 16);
    s.y += __shfl_xor_sync(0xffffffffu, s.y, 16);
    s.z += __shfl_xor_sync(0xffffffffu, s.z, 16);
    s.w += __shfl_xor_sync(0xffffffffu, s.w, 16);

    if ((t & 16) == 0)          // lanes 0-15 of each warp publish
        part[w * CB4 + c] = s;
    __syncthreads();

    // Tree-reduce 16 partials -> part[c]. Groups here are warps.
#pragma unroll
    for (int step = NPART / 2; step >= 1; step >>= 1) {
        if (w < step && (t & 16) == 0) {
            float4 a = part[w * CB4 + c];
            float4 b = part[(w + step) * CB4 + c];
            a.x += b.x; a.y += b.y; a.z += b.z; a.w += b.w;
            part[w * CB4 + c] = a;
        }
        __syncthreads();
    }

    const float inv = 1.0f / (float)K_ROWS;
    float4 m = part[c];          // broadcast read, conflict-free
    m.x *= inv; m.y *= inv; m.z *= inv; m.w *= inv;

    // CTA writes rows [rb*128, +128) of its 16-float4 column slice.
    // Group g writes 4 rows; branch-free (grid tiles 4096 exactly).
    int r0 = rb * ROWS_PER_CTA + g * (ROWS_PER_CTA / 32);
    size_t base = (size_t)r0 * COLS4 + col;
#pragma unroll
    for (int r = 0; r < ROWS_PER_CTA / 32; ++r) {
        out[base + (size_t)r * COLS4] = m;
    }
}

extern "C" void kernel_launch(void* const* d_in, const int* in_sizes, int n_in,
                              void* d_out, int out_size) {
    // d_in[0]: query_embedding [4,1024,512] f32 (unused — output is query-independent)
    // d_in[1]: knowledge [64,512] f32
    const float* knowledge = (const float*)d_in[1];
    float* out = (float*)d_out;

    int rows = out_size / E_DIM;                 // 4096
    int blocks = NCB * (rows / ROWS_PER_CTA);    // 256

    fused_mean_broadcast<<<blocks, THREADS>>>(
        reinterpret_cast<const float4*>(knowledge),
        reinterpret_cast<float4*>(out));
}

// round 12
// speedup vs baseline: 1.0465x; 1.0465x over previous
#include <cuda_runtime.h>
#include <cuda_bf16.h>

// Output[b,s,:] == mean(knowledge, axis=0) for every (b,s):
// top_k with max_chunks == K selects a permutation of ALL knowledge rows,
// so mean(take(knowledge, top_k), axis=1) == mean(knowledge, axis=0).
//
// Consolidation round: R9 (measured co-champion, 6.624us) with strictly
// less work: branch-free store tail (grid tiles 4096 rows exactly) and
// the reduce tree stopped one step early (last 2 partials folded into
// the final mean read -> one fewer __syncthreads round).
// Shape: 256 CTAs = 8 col-blocks x 32 row-blocks, 512 threads,
// 2 loads/thread, 4 coalesced STG.128/thread.

#define E_DIM 512
#define K_ROWS 64
#define THREADS 512
#define COLS4 (E_DIM / 4)       // 128 float4 per full row
#define NCB 8                   // column blocks
#define CB4 (COLS4 / NCB)       // 16 float4 columns per block
#define ROWS_PER_CTA 128        // 32 row-blocks cover 4096 rows
#define GROUPS 32               // 512 threads / 16 columns

__global__ void __launch_bounds__(THREADS)
fused_mean_broadcast(const float4* __restrict__ knowledge4,
                     float4* __restrict__ out) {
    __shared__ float4 part[GROUPS * CB4];   // 32 partials x 16 cols, 8KB

    int t = threadIdx.x;
    int c = t & (CB4 - 1);      // column within block: 0..15
    int g = t >> 4;             // group 0..31: sums rows [2g, 2g+2)

    int cb = blockIdx.x & (NCB - 1);   // column block 0..7
    int rb = blockIdx.x >> 3;          // row block 0..31
    int col = cb * CB4 + c;            // global float4 column

    // 2 independent front-batched loads per thread (coalesced).
    float4 a0 = knowledge4[(g * 2 + 0) * COLS4 + col];
    float4 a1 = knowledge4[(g * 2 + 1) * COLS4 + col];
    float4 s;
    s.x = a0.x + a1.x; s.y = a0.y + a1.y;
    s.z = a0.z + a1.z; s.w = a0.w + a1.w;
    part[g * CB4 + c] = s;
    __syncthreads();

    // Tree-reduce 32 -> 2 partials (4 steps; last combine folded below).
#pragma unroll
    for (int step = GROUPS / 2; step >= 2; step >>= 1) {
        if (g < step) {
            float4 a = part[g * CB4 + c];
            float4 b = part[(g + step) * CB4 + c];
            a.x += b.x; a.y += b.y; a.z += b.z; a.w += b.w;
            part[g * CB4 + c] = a;
        }
        __syncthreads();
    }

    // Final mean: sum the 2 surviving partials (conflict-free broadcast).
    const float inv = 1.0f / (float)K_ROWS;
    float4 p0 = part[c];
    float4 p1 = part[CB4 + c];
    float4 m;
    m.x = (p0.x + p1.x) * inv;
    m.y = (p0.y + p1.y) * inv;
    m.z = (p0.z + p1.z) * inv;
    m.w = (p0.w + p1.w) * inv;

    // CTA writes rows [rb*128, +128) of its 16-float4 column slice.
    // Group g writes 4 rows; branch-free (grid tiles 4096 exactly).
    int r0 = rb * ROWS_PER_CTA + g * (ROWS_PER_CTA / GROUPS);
    size_t base = (size_t)r0 * COLS4 + col;
#pragma unroll
    for (int r = 0; r < ROWS_PER_CTA / GROUPS; ++r) {
        out[base + (size_t)r * COLS4] = m;
    }
}

extern "C" void kernel_launch(void* const* d_in, const int* in_sizes, int n_in,
                              void* d_out, int out_size) {
    // d_in[0]: query_embedding [4,1024,512] f32 (unused — output is query-independent)
    // d_in[1]: knowledge [64,512] f32
    const float* knowledge = (const float*)d_in[1];
    float* out = (float*)d_out;

    int rows = out_size / E_DIM;                 // 4096
    int blocks = NCB * (rows / ROWS_PER_CTA);    // 256

    fused_mean_broadcast<<<blocks, THREADS>>>(
        reinterpret_cast<const float4*>(knowledge),
        reinterpret_cast<float4*>(out));
}

// round 13
// speedup vs baseline: 1.0817x; 1.0337x over previous
#include <cuda_runtime.h>
#include <cuda_bf16.h>

// Output[b,s,:] == mean(knowledge, axis=0) for every (b,s):
// top_k with max_chunks == K selects a permutation of ALL knowledge rows,
// so mean(take(knowledge, top_k), axis=1) == mean(knowledge, axis=0).
//
// R12 conclusion: all barrier/smem variants plateau at 6.6-6.9us; noise
// +/-0.2us. Last untried structure: WARP-AUTONOMOUS — zero smem, zero
// __syncthreads. Each warp owns 8 float4 columns; lanes = 4 row-groups
// x 8 cols; 16 front-batched loads/thread sum 16 rows; two shfl_xor
// (8,16) finish the 64-row column sum in-register; branch-free stores.
// 16 warps cover the full row; 128 CTAs x 32 rows (~one wave).

#define E_DIM 512
#define K_ROWS 64
#define THREADS 512
#define COLS4 (E_DIM / 4)       // 128 float4 per full row
#define ROWS_PER_CTA 32         // 4096 / 32 = 128 CTAs

__global__ void __launch_bounds__(THREADS)
fused_mean_broadcast(const float4* __restrict__ knowledge4,
                     float4* __restrict__ out) {
    int t = threadIdx.x;
    int lane = t & 31;
    int w = t >> 5;             // warp 0..15: owns float4 cols [8w, 8w+8)
    int c = lane & 7;           // column within warp slice
    int g = lane >> 3;          // row-group 0..3: rows [16g, 16g+16)

    int col = w * 8 + c;        // global float4 column

    // 16 independent front-batched loads (warp load = 8 full 128B sectors).
    float4 s = make_float4(0.f, 0.f, 0.f, 0.f);
#pragma unroll
    for (int k = 0; k < K_ROWS / 4; ++k) {
        float4 a = knowledge4[(g * (K_ROWS / 4) + k) * COLS4 + col];
        s.x += a.x; s.y += a.y; s.z += a.z; s.w += a.w;
    }

    // Lanes with the same c differ in bits 3,4 (the g bits): two xor
    // shuffles complete the 64-row sum. No smem, no barrier.
#pragma unroll
    for (int d = 8; d <= 16; d <<= 1) {
        s.x += __shfl_xor_sync(0xffffffffu, s.x, d);
        s.y += __shfl_xor_sync(0xffffffffu, s.y, d);
        s.z += __shfl_xor_sync(0xffffffffu, s.z, d);
        s.w += __shfl_xor_sync(0xffffffffu, s.w, d);
    }
    const float inv = 1.0f / (float)K_ROWS;
    s.x *= inv; s.y *= inv; s.z *= inv; s.w *= inv;

    // CTA writes rows [rb*32, +32). Replica-group g writes 8 of them.
    // Warp store = 4 x 128B full sectors. Branch-free (4096 % 32 == 0).
    int r0 = blockIdx.x * ROWS_PER_CTA + g * (ROWS_PER_CTA / 4);
    size_t base = (size_t)r0 * COLS4 + col;
#pragma unroll
    for (int r = 0; r < ROWS_PER_CTA / 4; ++r) {
        out[base + (size_t)r * COLS4] = s;
    }
}

extern "C" void kernel_launch(void* const* d_in, const int* in_sizes, int n_in,
                              void* d_out, int out_size) {
    // d_in[0]: query_embedding [4,1024,512] f32 (unused — output is query-independent)
    // d_in[1]: knowledge [64,512] f32
    const float* knowledge = (const float*)d_in[1];
    float* out = (float*)d_out;

    int rows = out_size / E_DIM;                 // 4096
    int blocks = rows / ROWS_PER_CTA;            // 128

    fused_mean_broadcast<<<blocks, THREADS>>>(
        reinterpret_cast<const float4*>(knowledge),
        reinterpret_cast<float4*>(out));
}